// round 13
// baseline (speedup 1.0000x reference)
#include <cuda_runtime.h>
#include <math.h>

// Problem constants
#define B_   8
#define C_   256
#define IC_  128
#define H_   128
#define W_   128
#define H2_  64
#define W2_  64
#define NQ_  4096     // 64*64
#define NKV_ 1024     // 32*32

// ------------------------- scratch (device globals; no allocation) -------------------------
__device__ float d_rgb_p[B_ * C_ * NQ_];      // [B][C][4096]
__device__ float d_ev_p [B_ * C_ * NQ_];      // [B][C][4096]
__device__ float d_theta[B_ * NQ_ * IC_];     // [B][4096][128]
__device__ float d_gconv[B_ * NQ_ * IC_];     // pre-pool g
__device__ float d_pconv[B_ * NQ_ * IC_];     // pre-pool phi
__device__ float d_g    [B_ * NKV_ * IC_];    // [B][1024][128]
__device__ float d_phi  [B_ * NKV_ * IC_];    // [B][1024][128]
__device__ float d_y    [B_ * NQ_ * IC_];     // [B][4096][128]
__device__ float d_wy   [B_ * C_ * NQ_];      // [B][256][4096]
__device__ float d_mean [C_];
__device__ float d_rstd [C_];

// ------------------------- helpers -------------------------
__device__ __forceinline__ float f2tf_f(float x) {
    unsigned u;
    asm("cvt.rna.tf32.f32 %0, %1;" : "=r"(u) : "f"(x));
    return __uint_as_float(u);
}
__device__ __forceinline__ unsigned fu(float x) { return __float_as_uint(x); }

__device__ __forceinline__ void mma8(float* c, const unsigned* a, const unsigned* b) {
    asm volatile(
        "mma.sync.aligned.m16n8k8.row.col.f32.tf32.tf32.f32 "
        "{%0,%1,%2,%3}, {%4,%5,%6,%7}, {%8,%9}, {%0,%1,%2,%3};\n"
        : "+f"(c[0]), "+f"(c[1]), "+f"(c[2]), "+f"(c[3])
        : "r"(a[0]), "r"(a[1]), "r"(a[2]), "r"(a[3]), "r"(b[0]), "r"(b[1]));
}

__device__ __forceinline__ void cpa16(void* s, const void* g) {
    unsigned ss = (unsigned)__cvta_generic_to_shared(s);
    asm volatile("cp.async.cg.shared.global [%0], [%1], 16;\n" :: "r"(ss), "l"(g));
}
#define CP_COMMIT() asm volatile("cp.async.commit_group;\n")
#define CP_WAIT0()  asm volatile("cp.async.wait_group 0;\n" ::: "memory")
#define CP_WAIT1()  asm volatile("cp.async.wait_group 1;\n" ::: "memory")

// ------------------------- generic GEMM infrastructure -------------------------
template<bool KMAJ> struct Tile;
template<> struct Tile<true>  { float d[2][16][136]; };
template<> struct Tile<false> { float d[2][128][20]; };

template<bool A_KMAJOR, bool B_KMAJOR, int BIAS_MODE>
__device__ __forceinline__ void gemm_body(
    const float* __restrict__ Ag, const float* __restrict__ Bg,
    const float* __restrict__ bias, float* __restrict__ Cg,
    int K, int Astride, int Bstride, int Cstride, int m0, int n0,
    Tile<A_KMAJOR>& As, Tile<B_KMAJOR>& Bs)
{
    int tid = threadIdx.x;
    int lane = tid & 31, warp = tid >> 5;
    int wm = warp >> 2, wn = warp & 3;           // 2 x 4 warps; warp tile 64m x 32n
    float acc[4][4][4] = {};
    int nkt = K / 16;

    auto stage = [&](int kt, int bf) {
        if constexpr (A_KMAJOR) {
            #pragma unroll
            for (int i = 0; i < 2; ++i) {
                int o = tid + i * 256;
                int r = o >> 5, c = (o & 31) << 2;
                cpa16(&As.d[bf][r][c], &Ag[(size_t)(kt * 16 + r) * Astride + c]);
            }
        } else {
            #pragma unroll
            for (int i = 0; i < 2; ++i) {
                int o = tid + i * 256;
                int r = o >> 2, c = (o & 3) << 2;
                cpa16(&As.d[bf][r][c], &Ag[(size_t)r * Astride + kt * 16 + c]);
            }
        }
        if constexpr (B_KMAJOR) {
            #pragma unroll
            for (int i = 0; i < 2; ++i) {
                int o = tid + i * 256;
                int r = o >> 5, c = (o & 31) << 2;
                cpa16(&Bs.d[bf][r][c], &Bg[(size_t)(kt * 16 + r) * Bstride + c]);
            }
        } else {
            #pragma unroll
            for (int i = 0; i < 2; ++i) {
                int o = tid + i * 256;
                int r = o >> 2, c = (o & 3) << 2;
                cpa16(&Bs.d[bf][r][c], &Bg[(size_t)r * Bstride + kt * 16 + c]);
            }
        }
    };

    stage(0, 0);
    CP_COMMIT();
    CP_WAIT0();
    __syncthreads();

    for (int kt = 0; kt < nkt; ++kt) {
        int cur = kt & 1;
        if (kt + 1 < nkt) stage(kt + 1, cur ^ 1);
        CP_COMMIT();

        #pragma unroll
        for (int ks = 0; ks < 16; ks += 8) {
            int kr = ks + (lane & 3);
            unsigned afh[4][4], afl[4][4], bfh[4][2], bfl[4][2];
            #pragma unroll
            for (int mi = 0; mi < 4; ++mi) {
                int mr = wm * 64 + mi * 16 + (lane >> 2);
                float v0, v1, v2, v3;
                if constexpr (A_KMAJOR) {
                    v0 = As.d[cur][kr][mr];     v1 = As.d[cur][kr][mr + 8];
                    v2 = As.d[cur][kr + 4][mr]; v3 = As.d[cur][kr + 4][mr + 8];
                } else {
                    v0 = As.d[cur][mr][kr];     v1 = As.d[cur][mr + 8][kr];
                    v2 = As.d[cur][mr][kr + 4]; v3 = As.d[cur][mr + 8][kr + 4];
                }
                float h;
                h = f2tf_f(v0); afh[mi][0] = fu(h); afl[mi][0] = fu(v0 - h);
                h = f2tf_f(v1); afh[mi][1] = fu(h); afl[mi][1] = fu(v1 - h);
                h = f2tf_f(v2); afh[mi][2] = fu(h); afl[mi][2] = fu(v2 - h);
                h = f2tf_f(v3); afh[mi][3] = fu(h); afl[mi][3] = fu(v3 - h);
            }
            #pragma unroll
            for (int ni = 0; ni < 4; ++ni) {
                int nc = wn * 32 + ni * 8 + (lane >> 2);
                float v0, v1;
                if constexpr (B_KMAJOR) {
                    v0 = Bs.d[cur][kr][nc]; v1 = Bs.d[cur][kr + 4][nc];
                } else {
                    v0 = Bs.d[cur][nc][kr]; v1 = Bs.d[cur][nc][kr + 4];
                }
                float h;
                h = f2tf_f(v0); bfh[ni][0] = fu(h); bfl[ni][0] = fu(v0 - h);
                h = f2tf_f(v1); bfh[ni][1] = fu(h); bfl[ni][1] = fu(v1 - h);
            }
            #pragma unroll
            for (int mi = 0; mi < 4; ++mi)
                #pragma unroll
                for (int ni = 0; ni < 4; ++ni) {
                    mma8(acc[mi][ni], afl[mi], bfh[ni]);   // lo*hi
                    mma8(acc[mi][ni], afh[mi], bfl[ni]);   // hi*lo
                    mma8(acc[mi][ni], afh[mi], bfh[ni]);   // hi*hi
                }
        }

        CP_WAIT0();
        __syncthreads();
    }

    #pragma unroll
    for (int mi = 0; mi < 4; ++mi) {
        int r0 = m0 + wm * 64 + mi * 16 + (lane >> 2);
        #pragma unroll
        for (int ni = 0; ni < 4; ++ni) {
            int c0i = n0 + wn * 32 + ni * 8 + 2 * (lane & 3);
            float a0 = 0.f, a1 = 0.f, b0v = 0.f, b1v = 0.f;
            if (BIAS_MODE == 1) { a0 = bias[c0i]; a1 = bias[c0i + 1]; b0v = a0; b1v = a1; }
            if (BIAS_MODE == 2) { a0 = a1 = bias[r0]; b0v = b1v = bias[r0 + 8]; }
            float2 v0 = { acc[mi][ni][0] + a0, acc[mi][ni][1] + a1 };
            float2 v1 = { acc[mi][ni][2] + b0v, acc[mi][ni][3] + b1v };
            *(float2*)&Cg[(size_t)r0 * Cstride + c0i] = v0;
            *(float2*)&Cg[(size_t)(r0 + 8) * Cstride + c0i] = v1;
        }
    }
}

template<bool A_KMAJOR, bool B_KMAJOR, int BIAS_MODE>
__global__ void __launch_bounds__(256) gemm_tc(
    const float* __restrict__ A, const float* __restrict__ Bm,
    const float* __restrict__ bias, float* __restrict__ Cm,
    int K, int Astride, int Bstride, int Cstride,
    long sAb, long sBb, long sCb)
{
    __shared__ Tile<A_KMAJOR> As;
    __shared__ Tile<B_KMAJOR> Bs;
    int m0 = blockIdx.x * 128, n0 = blockIdx.y * 128;
    int b = blockIdx.z;
    const float* Ag = A + (size_t)b * sAb;
    const float* Bg = Bm + (size_t)b * sBb;
    float* Cg = Cm + (size_t)b * sCb;
    if (A_KMAJOR) Ag += m0; else Ag += (size_t)m0 * Astride;
    if (B_KMAJOR) Bg += n0; else Bg += (size_t)n0 * Bstride;
    gemm_body<A_KMAJOR, B_KMAJOR, BIAS_MODE>(
        Ag, Bg, bias, Cg, K, Astride, Bstride, Cstride, m0, n0, As, Bs);
}

// merged projection kernel (theta/g/phi), z = proj*8 + b
__global__ void __launch_bounds__(256) gemm_proj(
    const float* __restrict__ rgb_p, const float* __restrict__ ev_p,
    const float* __restrict__ tw, const float* __restrict__ tb,
    const float* __restrict__ gw, const float* __restrict__ gb,
    const float* __restrict__ pw, const float* __restrict__ pb,
    float* __restrict__ theta, float* __restrict__ gconv, float* __restrict__ pconv)
{
    __shared__ Tile<true> As;
    __shared__ Tile<false> Bs;
    int z = blockIdx.z;
    int pz = z >> 3, b = z & 7;
    const float* Aall = (pz == 0) ? rgb_p : ev_p;
    const float* Bw   = (pz == 0) ? tw : (pz == 1 ? gw : pw);
    const float* bias = (pz == 0) ? tb : (pz == 1 ? gb : pb);
    float* Cm         = (pz == 0) ? theta : (pz == 1 ? gconv : pconv);
    int m0 = blockIdx.x * 128;
    const float* Ag = Aall + (size_t)b * C_ * NQ_ + m0;   // k-major [256][4096]
    float* Cg = Cm + (size_t)b * NQ_ * IC_;
    gemm_body<true, false, 1>(Ag, Bw, bias, Cg, C_, NQ_, C_, IC_, m0, 0, As, Bs);
}

// ------------------------- fused flash attention (3xTF32 tensor cores) -------------------------
// Q = d_theta [B][4096][128], K = d_phi [B][1024][128], V = d_g [B][1024][128]
// y[b][q][:] = softmax_kv(Q·K^T) @ V.  Warp owns 16 q-rows x full kv width.
// V rows stored permuted within 8-groups (sigma(j) = ((j&3)<<1)|bit2(j)) so the S
// C-fragment is directly reusable as the PV A-fragment (a = {c0,c2,c1,c3}).
#define SMEM_ATTN ((128 * 132 * 2 + 128 * 136) * 4)

__global__ void __launch_bounds__(256, 1) attn_fused() {
    extern __shared__ float sm_att[];
    float* Qs = sm_att;                  // [128][132]
    float* Ks = sm_att + 128 * 132;      // [128][132]
    float* Vs = sm_att + 2 * 128 * 132;  // [128][136]

    int tid = threadIdx.x;
    int lane = tid & 31, warp = tid >> 5;
    int gr = lane >> 2, b4 = lane & 3;
    int bb = blockIdx.y;
    int q0 = blockIdx.x * 128;

    const float* Qg = d_theta + ((size_t)bb * NQ_ + q0) * IC_;
    const float* Kg = d_phi + (size_t)bb * NKV_ * IC_;
    const float* Vg = d_g   + (size_t)bb * NKV_ * IC_;

    int r0 = warp * 16 + gr;
    int r1 = r0 + 8;

    // stage Q + K0 (group), V0 (group) — 128 rows x 128 floats = 4096 x 16B chunks each
    #pragma unroll
    for (int i = 0; i < 16; ++i) {
        int idx = tid + i * 256, r = idx >> 5, ch = (idx & 31) << 2;   // FIX: full tile
        cpa16(Qs + r * 132 + ch, Qg + r * 128 + ch);
        cpa16(Ks + r * 132 + ch, Kg + r * 128 + ch);
    }
    CP_COMMIT();
    #pragma unroll
    for (int i = 0; i < 16; ++i) {
        int idx = tid + i * 256, r = idx >> 5, ch = (idx & 31) << 2;   // FIX: full tile
        int pr = (r & ~7) | (((r & 3) << 1) | ((r >> 2) & 1));
        cpa16(Vs + r * 136 + ch, Vg + pr * 128 + ch);
    }
    CP_COMMIT();
    CP_WAIT1();               // Q, K0 ready (V0 may be pending)
    __syncthreads();

    float O[16][4] = {};
    float m0 = -INFINITY, m1 = -INFINITY, l0 = 0.f, l1 = 0.f;

    #pragma unroll 1
    for (int t = 0; t < 8; ++t) {
        // ---- S = Q @ K_t^T  (warp: 16 q-rows x 128 kv) ----
        float sf[16][4] = {};
        #pragma unroll
        for (int kt = 0; kt < 16; ++kt) {
            int kq = kt * 8 + b4;
            float v0 = Qs[r0 * 132 + kq],     v1 = Qs[r1 * 132 + kq];
            float v2 = Qs[r0 * 132 + kq + 4], v3 = Qs[r1 * 132 + kq + 4];
            unsigned ah[4], al[4];
            float h;
            h = f2tf_f(v0); ah[0] = fu(h); al[0] = fu(v0 - h);
            h = f2tf_f(v1); ah[1] = fu(h); al[1] = fu(v1 - h);
            h = f2tf_f(v2); ah[2] = fu(h); al[2] = fu(v2 - h);
            h = f2tf_f(v3); ah[3] = fu(h); al[3] = fu(v3 - h);
            #pragma unroll
            for (int ni = 0; ni < 16; ++ni) {
                float w0 = Ks[(ni * 8 + gr) * 132 + kq];
                float w1 = Ks[(ni * 8 + gr) * 132 + kq + 4];
                unsigned bh[2], bl[2];
                h = f2tf_f(w0); bh[0] = fu(h); bl[0] = fu(w0 - h);
                h = f2tf_f(w1); bh[1] = fu(h); bl[1] = fu(w1 - h);
                mma8(sf[ni], al, bh);
                mma8(sf[ni], ah, bl);
                mma8(sf[ni], ah, bh);
            }
        }

        // ---- online softmax (registers; rows r0, r1 per thread; quad reduce) ----
        {
            float mx0 = -INFINITY, mx1 = -INFINITY;
            #pragma unroll
            for (int ni = 0; ni < 16; ++ni) {
                mx0 = fmaxf(mx0, fmaxf(sf[ni][0], sf[ni][1]));
                mx1 = fmaxf(mx1, fmaxf(sf[ni][2], sf[ni][3]));
            }
            mx0 = fmaxf(mx0, __shfl_xor_sync(0xffffffffu, mx0, 1));
            mx0 = fmaxf(mx0, __shfl_xor_sync(0xffffffffu, mx0, 2));
            mx1 = fmaxf(mx1, __shfl_xor_sync(0xffffffffu, mx1, 1));
            mx1 = fmaxf(mx1, __shfl_xor_sync(0xffffffffu, mx1, 2));
            float m0n = fmaxf(m0, mx0), m1n = fmaxf(m1, mx1);
            float sc0 = __expf(m0 - m0n), sc1 = __expf(m1 - m1n);
            float ps0 = 0.f, ps1 = 0.f;
            #pragma unroll
            for (int ni = 0; ni < 16; ++ni) {
                sf[ni][0] = __expf(sf[ni][0] - m0n); ps0 += sf[ni][0];
                sf[ni][1] = __expf(sf[ni][1] - m0n); ps0 += sf[ni][1];
                sf[ni][2] = __expf(sf[ni][2] - m1n); ps1 += sf[ni][2];
                sf[ni][3] = __expf(sf[ni][3] - m1n); ps1 += sf[ni][3];
            }
            ps0 += __shfl_xor_sync(0xffffffffu, ps0, 1);
            ps0 += __shfl_xor_sync(0xffffffffu, ps0, 2);
            ps1 += __shfl_xor_sync(0xffffffffu, ps1, 1);
            ps1 += __shfl_xor_sync(0xffffffffu, ps1, 2);
            l0 = l0 * sc0 + ps0; l1 = l1 * sc1 + ps1;
            m0 = m0n; m1 = m1n;
            #pragma unroll
            for (int ni = 0; ni < 16; ++ni) {
                O[ni][0] *= sc0; O[ni][1] *= sc0;
                O[ni][2] *= sc1; O[ni][3] *= sc1;
            }
        }

        __syncthreads();                         // all warps done reading Ks
        if (t < 7) {                             // prefetch K_{t+1} during PV
            #pragma unroll
            for (int i = 0; i < 16; ++i) {
                int idx = tid + i * 256, r = idx >> 5, ch = (idx & 31) << 2;
                cpa16(Ks + r * 132 + ch, Kg + ((t + 1) * 128 + r) * 128 + ch);
            }
            CP_COMMIT();
            CP_WAIT1();                          // V_t arrived (K_{t+1} pending)
        } else {
            CP_WAIT0();                          // last tile — drain V_7 fully
        }
        __syncthreads();

        // ---- O += P @ V_t  (P = sf fragments, zero-shuffle reuse) ----
        #pragma unroll
        for (int kt = 0; kt < 16; ++kt) {
            float p0 = sf[kt][0], p1 = sf[kt][2], p2 = sf[kt][1], p3 = sf[kt][3];
            unsigned ph[4], pl[4];
            float h;
            h = f2tf_f(p0); ph[0] = fu(h); pl[0] = fu(p0 - h);
            h = f2tf_f(p1); ph[1] = fu(h); pl[1] = fu(p1 - h);
            h = f2tf_f(p2); ph[2] = fu(h); pl[2] = fu(p2 - h);
            h = f2tf_f(p3); ph[3] = fu(h); pl[3] = fu(p3 - h);
            #pragma unroll
            for (int ni = 0; ni < 16; ++ni) {
                float w0 = Vs[(kt * 8 + b4) * 136 + ni * 8 + gr];
                float w1 = Vs[(kt * 8 + b4 + 4) * 136 + ni * 8 + gr];
                unsigned bh[2], bl[2];
                h = f2tf_f(w0); bh[0] = fu(h); bl[0] = fu(w0 - h);
                h = f2tf_f(w1); bh[1] = fu(h); bl[1] = fu(w1 - h);
                mma8(O[ni], pl, bh);
                mma8(O[ni], ph, bl);
                mma8(O[ni], ph, bh);
            }
        }

        __syncthreads();                         // all warps done reading Vs
        if (t < 7) {                             // prefetch V_{t+1} (permuted rows)
            #pragma unroll
            for (int i = 0; i < 16; ++i) {
                int idx = tid + i * 256, r = idx >> 5, ch = (idx & 31) << 2;
                int pr = (r & ~7) | (((r & 3) << 1) | ((r >> 2) & 1));
                cpa16(Vs + r * 136 + ch, Vg + ((t + 1) * 128 + pr) * 128 + ch);
            }
            CP_COMMIT();
            CP_WAIT1();                          // K_{t+1} arrived (V_{t+1} pending)
            __syncthreads();
        }
    }

    // ---- epilogue: y = O / l ----
    float inv0 = 1.f / l0, inv1 = 1.f / l1;
    float* yb = d_y + ((size_t)bb * NQ_ + q0) * IC_;
    #pragma unroll
    for (int ni = 0; ni < 16; ++ni) {
        int c = ni * 8 + 2 * b4;
        float2 v0 = { O[ni][0] * inv0, O[ni][1] * inv0 };
        float2 v1 = { O[ni][2] * inv1, O[ni][3] * inv1 };
        *(float2*)&yb[(size_t)r0 * IC_ + c] = v0;
        *(float2*)&yb[(size_t)r1 * IC_ + c] = v1;
    }
}

// ------------------------- 2x2 maxpool NCHW, vectorized (2 outputs/thread) -------------------------
__global__ void pool2_kernel(const float* __restrict__ in, float* __restrict__ out, int n) {
    int i = blockIdx.x * blockDim.x + threadIdx.x;
    if (i >= n) return;                      // n = B*C*64*32
    int ow2 = i & 31;
    int t  = i >> 5;
    int oh = t & 63;
    int bc = t >> 6;
    const float* p = in + ((size_t)bc * H_ + 2 * oh) * W_ + ow2 * 4;
    float4 a = *(const float4*)p;
    float4 c = *(const float4*)(p + W_);
    float2 r;
    r.x = fmaxf(fmaxf(a.x, a.y), fmaxf(c.x, c.y));
    r.y = fmaxf(fmaxf(a.z, a.w), fmaxf(c.z, c.w));
    *(float2*)&out[((size_t)bc * H2_ + oh) * W2_ + ow2 * 2] = r;
}

// ------------------------- row-pool [B][4096][128] -> [B][1024][128] -------------------------
__global__ void poolrows_kernel(const float* __restrict__ in, float* __restrict__ out, int n) {
    int i = blockIdx.x * blockDim.x + threadIdx.x;
    if (i >= n) return;                      // n = B*1024*32 (float4 units)
    int ic4 = i & 31;
    int kv  = (i >> 5) & 1023;
    int b   = i >> 15;
    int ph = kv >> 5, pw = kv & 31;
    int s00 = (ph * 2) * 64 + pw * 2;
    const float4* p = (const float4*)(in + ((size_t)b * NQ_ + s00) * IC_) + ic4;
    float4 a = p[0], c = p[32], d = p[64 * 32], e = p[65 * 32];
    float4 r;
    r.x = fmaxf(fmaxf(a.x, c.x), fmaxf(d.x, e.x));
    r.y = fmaxf(fmaxf(a.y, c.y), fmaxf(d.y, e.y));
    r.z = fmaxf(fmaxf(a.z, c.z), fmaxf(d.z, e.z));
    r.w = fmaxf(fmaxf(a.w, c.w), fmaxf(d.w, e.w));
    ((float4*)(out + ((size_t)b * NKV_ + kv) * IC_))[ic4] = r;
}

// ------------------------- BatchNorm stats (deterministic, float4) -------------------------
__global__ void bnstats_kernel() {
    __shared__ float ss[256], ss2[256];
    int co = blockIdx.x, tid = threadIdx.x;
    float s = 0.f, s2 = 0.f;
    for (int i = tid; i < B_ * NQ_ / 4; i += 256) {
        int b = i >> 10, sp = (i & 1023) << 2;
        float4 v = *(const float4*)&d_wy[((size_t)b * C_ + co) * NQ_ + sp];
        s += (v.x + v.y) + (v.z + v.w);
        s2 += (v.x * v.x + v.y * v.y) + (v.z * v.z + v.w * v.w);
    }
    ss[tid] = s; ss2[tid] = s2;
    __syncthreads();
    for (int st = 128; st > 0; st >>= 1) {
        if (tid < st) { ss[tid] += ss[tid + st]; ss2[tid] += ss2[tid + st]; }
        __syncthreads();
    }
    if (tid == 0) {
        const float invN = 1.f / (B_ * NQ_);
        float mean = ss[0] * invN;
        float var  = ss2[0] * invN - mean * mean;
        d_mean[co] = mean;
        d_rstd[co] = rsqrtf(var + 1e-5f);
    }
}

// ------------------------- BN apply + residual + 2x upsample -------------------------
// One thread per source element-pair: reads wy/rgb once, writes 2 rows x float4.
__global__ void final_kernel(const float* __restrict__ gamma, const float* __restrict__ beta,
                             float* __restrict__ out, int n) {
    int i = blockIdx.x * blockDim.x + threadIdx.x;
    if (i >= n) return;                      // n = B*C*64*32
    int w2p = i & 31;                        // pair of pooled cols: 2*w2p, 2*w2p+1
    int h2  = (i >> 5) & 63;
    int co  = (i >> 11) & 255;
    int b   = i >> 19;
    size_t base = ((size_t)b * C_ + co) * NQ_ + h2 * W2_ + 2 * w2p;
    float mn = d_mean[co], rs = d_rstd[co], gm = gamma[co], bt = beta[co];
    float2 wyv = *(const float2*)&d_wy[base];
    float2 rgv = *(const float2*)&d_rgb_p[base];
    float va = (wyv.x - mn) * rs * gm + bt + rgv.x;
    float vb = (wyv.y - mn) * rs * gm + bt + rgv.y;
    float4 r = { va, va, vb, vb };
    size_t ob = (((size_t)b * C_ + co) * H_ + 2 * h2) * W_ + 4 * w2p;
    *(float4*)&out[ob]      = r;             // row 2*h2
    *(float4*)&out[ob + W_] = r;             // row 2*h2+1
}

// ------------------------- launch -------------------------
extern "C" void kernel_launch(void* const* d_in, const int* in_sizes, int n_in,
                              void* d_out, int out_size) {
    const float* rgb     = (const float*)d_in[0];
    const float* event_  = (const float*)d_in[1];
    const float* g_w     = (const float*)d_in[2];
    const float* g_b     = (const float*)d_in[3];
    const float* theta_w = (const float*)d_in[4];
    const float* theta_b = (const float*)d_in[5];
    const float* phi_w   = (const float*)d_in[6];
    const float* phi_b   = (const float*)d_in[7];
    const float* W_w     = (const float*)d_in[8];
    const float* W_b     = (const float*)d_in[9];
    const float* bn_g    = (const float*)d_in[10];
    const float* bn_b    = (const float*)d_in[11];
    float* out = (float*)d_out;

    float *rgb_p, *ev_p, *theta, *gconv, *pconv, *g, *phi, *y, *wy;
    cudaGetSymbolAddress((void**)&rgb_p, d_rgb_p);
    cudaGetSymbolAddress((void**)&ev_p,  d_ev_p);
    cudaGetSymbolAddress((void**)&theta, d_theta);
    cudaGetSymbolAddress((void**)&gconv, d_gconv);
    cudaGetSymbolAddress((void**)&pconv, d_pconv);
    cudaGetSymbolAddress((void**)&g,     d_g);
    cudaGetSymbolAddress((void**)&phi,   d_phi);
    cudaGetSymbolAddress((void**)&y,     d_y);
    cudaGetSymbolAddress((void**)&wy,    d_wy);

    // opt-in to >48KB dynamic smem for the fused attention kernel (idempotent)
    cudaFuncSetAttribute(attn_fused, cudaFuncAttributeMaxDynamicSharedMemorySize, SMEM_ATTN);

    // 1) initial 2x2 maxpool on both modalities (2 outputs/thread)
    {
        int n = B_ * C_ * H2_ * W2_ / 2;
        pool2_kernel<<<(n + 255) / 256, 256>>>(rgb,    rgb_p, n);
        pool2_kernel<<<(n + 255) / 256, 256>>>(event_, ev_p,  n);
    }
    // 2) merged 1x1 conv projections (theta, g, phi) in one launch
    {
        dim3 grid(NQ_ / 128, 1, 24);
        gemm_proj<<<grid, 256>>>(rgb_p, ev_p, theta_w, theta_b, g_w, g_b,
                                 phi_w, phi_b, theta, gconv, pconv);
    }
    // 3) sub-sample pool for g and phi
    {
        int n = B_ * NKV_ * (IC_ / 4);
        poolrows_kernel<<<(n + 255) / 256, 256>>>(gconv, g,   n);
        poolrows_kernel<<<(n + 255) / 256, 256>>>(pconv, phi, n);
    }
    // 4) fused flash attention: y = softmax(theta @ phi^T) @ g
    {
        dim3 grid(NQ_ / 128, B_);
        attn_fused<<<grid, 256, SMEM_ATTN>>>();
    }
    // 5) output conv: wy[b][co][s] = sum_ic W_w[co][ic] y[b][s][ic] + W_b[co]
    {
        dim3 grid(C_ / 128, NQ_ / 128, B_);
        gemm_tc<false, false, 2><<<grid, 256>>>(W_w, y, W_b, wy,
            IC_, IC_, IC_, NQ_, 0, (long)NQ_ * IC_, (long)C_ * NQ_);
    }
    // 6) BN stats
    bnstats_kernel<<<C_, 256>>>();
    // 7) BN apply + residual + 2x upsample
    {
        int n = B_ * C_ * H2_ * W2_ / 2;
        final_kernel<<<(n + 255) / 256, 256>>>(bn_g, bn_b, out, n);
    }
}

// round 14
// speedup vs baseline: 1.5987x; 1.5987x over previous
#include <cuda_runtime.h>
#include <cuda_bf16.h>
#include <math.h>

// Problem constants
#define B_   8
#define C_   256
#define IC_  128
#define H_   128
#define W_   128
#define H2_  64
#define W2_  64
#define NQ_  4096     // 64*64
#define NKV_ 1024     // 32*32

// ------------------------- scratch (device globals; no allocation) -------------------------
__device__ float d_rgb_p[B_ * C_ * NQ_];      // [B][C][4096]
__device__ float d_ev_p [B_ * C_ * NQ_];      // [B][C][4096]
__device__ float d_theta[B_ * NQ_ * IC_];     // [B][4096][128]
__device__ float d_gconv[B_ * NQ_ * IC_];     // pre-pool g
__device__ float d_pconv[B_ * NQ_ * IC_];     // pre-pool phi
__device__ float d_g    [B_ * NKV_ * IC_];    // [B][1024][128]
__device__ float d_phi  [B_ * NKV_ * IC_];    // [B][1024][128]
__device__ float d_S    [B_ * NQ_ * NKV_];    // [B][4096][1024] scores/probs
__device__ float d_y    [B_ * NQ_ * IC_];     // [B][4096][128]
__device__ float d_wy   [B_ * C_ * NQ_];      // [B][256][4096]
__device__ float d_mean [C_];
__device__ float d_rstd [C_];

// ------------------------- helpers -------------------------
// Split a pair of consecutive-k fp32 values into packed bf16x2 hi and lo.
// hi = bf16_rn(v); lo = bf16_rn(v - hi)  (v - hi is exact in fp32).
// Packing: low half = v0 (even k), high half = v1 (odd k) — matches m16n8k16 frag order.
__device__ __forceinline__ void split2(float v0, float v1, unsigned &hi, unsigned &lo) {
    unsigned h;
    asm("cvt.rn.bf16x2.f32 %0, %1, %2;" : "=r"(h) : "f"(v1), "f"(v0));
    float h0 = __uint_as_float(h << 16);
    float h1 = __uint_as_float(h & 0xFFFF0000u);
    float r0 = v0 - h0, r1 = v1 - h1;
    asm("cvt.rn.bf16x2.f32 %0, %1, %2;" : "=r"(lo) : "f"(r1), "f"(r0));
    hi = h;
}

__device__ __forceinline__ void mma16(float* c, const unsigned* a, const unsigned* b) {
    asm volatile(
        "mma.sync.aligned.m16n8k16.row.col.f32.bf16.bf16.f32 "
        "{%0,%1,%2,%3}, {%4,%5,%6,%7}, {%8,%9}, {%0,%1,%2,%3};\n"
        : "+f"(c[0]), "+f"(c[1]), "+f"(c[2]), "+f"(c[3])
        : "r"(a[0]), "r"(a[1]), "r"(a[2]), "r"(a[3]), "r"(b[0]), "r"(b[1]));
}

__device__ __forceinline__ void cpa16(void* s, const void* g) {
    unsigned ss = (unsigned)__cvta_generic_to_shared(s);
    asm volatile("cp.async.cg.shared.global [%0], [%1], 16;\n" :: "r"(ss), "l"(g));
}
#define CP_COMMIT() asm volatile("cp.async.commit_group;\n")
#define CP_WAIT0()  asm volatile("cp.async.wait_group 0;\n" ::: "memory")

// ------------------------- generic GEMM infrastructure -------------------------
// k-major: [k=16][val 128 pad 132]  (scalar frag loads: bank = 8t+gr, conflict-free)
// m-major: [m/n=128][k=16 pad 20]   (float2 frag loads, <=2-way)
template<bool KMAJ> struct Tile;
template<> struct Tile<true>  { float d[2][16][132]; };
template<> struct Tile<false> { float d[2][128][20]; };

// ------------------------- 3-term split-bf16 GEMM body -------------------------
// C[m][n] = sum_k A(m,k)*B(k,n) (+bias). 128x128 block tile, ktile 16 (one
// m16n8k16 k-step per tile), cp.async 2-stage double buffer.
// product = lo*hi + hi*lo + hi*hi (fp32 accumulate; error ~2^-18/elem).
template<bool A_KMAJOR, bool B_KMAJOR, int BIAS_MODE>
__device__ __forceinline__ void gemm_body(
    const float* __restrict__ Ag, const float* __restrict__ Bg,
    const float* __restrict__ bias, float* __restrict__ Cg,
    int K, int Astride, int Bstride, int Cstride, int m0, int n0,
    Tile<A_KMAJOR>& As, Tile<B_KMAJOR>& Bs)
{
    int tid = threadIdx.x;
    int lane = tid & 31, warp = tid >> 5;
    int wm = warp >> 2, wn = warp & 3;           // 2 x 4 warps; warp tile 64m x 32n
    float acc[4][4][4] = {};
    int nkt = K / 16;

    auto stage = [&](int kt, int bf) {
        if constexpr (A_KMAJOR) {
            #pragma unroll
            for (int i = 0; i < 2; ++i) {
                int o = tid + i * 256;
                int r = o >> 5, c = (o & 31) << 2;
                cpa16(&As.d[bf][r][c], &Ag[(size_t)(kt * 16 + r) * Astride + c]);
            }
        } else {
            #pragma unroll
            for (int i = 0; i < 2; ++i) {
                int o = tid + i * 256;
                int r = o >> 2, c = (o & 3) << 2;
                cpa16(&As.d[bf][r][c], &Ag[(size_t)r * Astride + kt * 16 + c]);
            }
        }
        if constexpr (B_KMAJOR) {
            #pragma unroll
            for (int i = 0; i < 2; ++i) {
                int o = tid + i * 256;
                int r = o >> 5, c = (o & 31) << 2;
                cpa16(&Bs.d[bf][r][c], &Bg[(size_t)(kt * 16 + r) * Bstride + c]);
            }
        } else {
            #pragma unroll
            for (int i = 0; i < 2; ++i) {
                int o = tid + i * 256;
                int r = o >> 2, c = (o & 3) << 2;
                cpa16(&Bs.d[bf][r][c], &Bg[(size_t)r * Bstride + kt * 16 + c]);
            }
        }
    };

    stage(0, 0);
    CP_COMMIT();
    CP_WAIT0();
    __syncthreads();

    for (int kt = 0; kt < nkt; ++kt) {
        int cur = kt & 1;
        if (kt + 1 < nkt) stage(kt + 1, cur ^ 1);
        CP_COMMIT();

        // ---- one m16n8k16 k-step over this 16-wide k-tile ----
        int kb = (lane & 3) * 2;
        unsigned ah[4][4], al[4][4], bh[4][2], bl[4][2];
        // A fragment regs: 0:(mr,kb) 1:(mr+8,kb) 2:(mr,kb+8) 3:(mr+8,kb+8)
        #pragma unroll
        for (int mi = 0; mi < 4; ++mi) {
            int mr = wm * 64 + mi * 16 + (lane >> 2);
            if constexpr (A_KMAJOR) {
                split2(As.d[cur][kb][mr],       As.d[cur][kb + 1][mr],       ah[mi][0], al[mi][0]);
                split2(As.d[cur][kb][mr + 8],   As.d[cur][kb + 1][mr + 8],   ah[mi][1], al[mi][1]);
                split2(As.d[cur][kb + 8][mr],   As.d[cur][kb + 9][mr],       ah[mi][2], al[mi][2]);
                split2(As.d[cur][kb + 8][mr + 8], As.d[cur][kb + 9][mr + 8], ah[mi][3], al[mi][3]);
            } else {
                float2 v;
                v = *(const float2*)&As.d[cur][mr][kb];         split2(v.x, v.y, ah[mi][0], al[mi][0]);
                v = *(const float2*)&As.d[cur][mr + 8][kb];     split2(v.x, v.y, ah[mi][1], al[mi][1]);
                v = *(const float2*)&As.d[cur][mr][kb + 8];     split2(v.x, v.y, ah[mi][2], al[mi][2]);
                v = *(const float2*)&As.d[cur][mr + 8][kb + 8]; split2(v.x, v.y, ah[mi][3], al[mi][3]);
            }
        }
        // B fragment regs: 0:(kb..kb+1, nc) 1:(kb+8..kb+9, nc)
        #pragma unroll
        for (int ni = 0; ni < 4; ++ni) {
            int nc = wn * 32 + ni * 8 + (lane >> 2);
            if constexpr (B_KMAJOR) {
                split2(Bs.d[cur][kb][nc],     Bs.d[cur][kb + 1][nc], bh[ni][0], bl[ni][0]);
                split2(Bs.d[cur][kb + 8][nc], Bs.d[cur][kb + 9][nc], bh[ni][1], bl[ni][1]);
            } else {
                float2 v;
                v = *(const float2*)&Bs.d[cur][nc][kb];     split2(v.x, v.y, bh[ni][0], bl[ni][0]);
                v = *(const float2*)&Bs.d[cur][nc][kb + 8]; split2(v.x, v.y, bh[ni][1], bl[ni][1]);
            }
        }
        #pragma unroll
        for (int mi = 0; mi < 4; ++mi)
            #pragma unroll
            for (int ni = 0; ni < 4; ++ni) {
                mma16(acc[mi][ni], al[mi], bh[ni]);   // lo*hi
                mma16(acc[mi][ni], ah[mi], bl[ni]);   // hi*lo
                mma16(acc[mi][ni], ah[mi], bh[ni]);   // hi*hi
            }

        CP_WAIT0();
        __syncthreads();
    }

    #pragma unroll
    for (int mi = 0; mi < 4; ++mi) {
        int r0 = m0 + wm * 64 + mi * 16 + (lane >> 2);
        #pragma unroll
        for (int ni = 0; ni < 4; ++ni) {
            int c0i = n0 + wn * 32 + ni * 8 + 2 * (lane & 3);
            float a0 = 0.f, a1 = 0.f, b0v = 0.f, b1v = 0.f;
            if (BIAS_MODE == 1) { a0 = bias[c0i]; a1 = bias[c0i + 1]; b0v = a0; b1v = a1; }
            if (BIAS_MODE == 2) { a0 = a1 = bias[r0]; b0v = b1v = bias[r0 + 8]; }
            float2 v0 = { acc[mi][ni][0] + a0, acc[mi][ni][1] + a1 };
            float2 v1 = { acc[mi][ni][2] + b0v, acc[mi][ni][3] + b1v };
            *(float2*)&Cg[(size_t)r0 * Cstride + c0i] = v0;
            *(float2*)&Cg[(size_t)(r0 + 8) * Cstride + c0i] = v1;
        }
    }
}

template<bool A_KMAJOR, bool B_KMAJOR, int BIAS_MODE>
__global__ void __launch_bounds__(256) gemm_tc(
    const float* __restrict__ A, const float* __restrict__ Bm,
    const float* __restrict__ bias, float* __restrict__ Cm,
    int K, int Astride, int Bstride, int Cstride,
    long sAb, long sBb, long sCb)
{
    __shared__ Tile<A_KMAJOR> As;
    __shared__ Tile<B_KMAJOR> Bs;
    int m0 = blockIdx.x * 128, n0 = blockIdx.y * 128;
    int b = blockIdx.z;
    const float* Ag = A + (size_t)b * sAb;
    const float* Bg = Bm + (size_t)b * sBb;
    float* Cg = Cm + (size_t)b * sCb;
    if (A_KMAJOR) Ag += m0; else Ag += (size_t)m0 * Astride;
    if (B_KMAJOR) Bg += n0; else Bg += (size_t)n0 * Bstride;
    gemm_body<A_KMAJOR, B_KMAJOR, BIAS_MODE>(
        Ag, Bg, bias, Cg, K, Astride, Bstride, Cstride, m0, n0, As, Bs);
}

// merged projection kernel (theta/g/phi), z = proj*8 + b
__global__ void __launch_bounds__(256) gemm_proj(
    const float* __restrict__ rgb_p, const float* __restrict__ ev_p,
    const float* __restrict__ tw, const float* __restrict__ tb,
    const float* __restrict__ gw, const float* __restrict__ gb,
    const float* __restrict__ pw, const float* __restrict__ pb,
    float* __restrict__ theta, float* __restrict__ gconv, float* __restrict__ pconv)
{
    __shared__ Tile<true> As;
    __shared__ Tile<false> Bs;
    int z = blockIdx.z;
    int pz = z >> 3, b = z & 7;
    const float* Aall = (pz == 0) ? rgb_p : ev_p;
    const float* Bw   = (pz == 0) ? tw : (pz == 1 ? gw : pw);
    const float* bias = (pz == 0) ? tb : (pz == 1 ? gb : pb);
    float* Cm         = (pz == 0) ? theta : (pz == 1 ? gconv : pconv);
    int m0 = blockIdx.x * 128;
    const float* Ag = Aall + (size_t)b * C_ * NQ_ + m0;   // k-major [256][4096]
    float* Cg = Cm + (size_t)b * NQ_ * IC_;
    gemm_body<true, false, 1>(Ag, Bw, bias, Cg, C_, NQ_, C_, IC_, m0, 0, As, Bs);
}

// ------------------------- 2x2 maxpool NCHW, vectorized (2 outputs/thread) -------------------------
__global__ void pool2_kernel(const float* __restrict__ in, float* __restrict__ out, int n) {
    int i = blockIdx.x * blockDim.x + threadIdx.x;
    if (i >= n) return;                      // n = B*C*64*32
    int ow2 = i & 31;
    int t  = i >> 5;
    int oh = t & 63;
    int bc = t >> 6;
    const float* p = in + ((size_t)bc * H_ + 2 * oh) * W_ + ow2 * 4;
    float4 a = *(const float4*)p;
    float4 c = *(const float4*)(p + W_);
    float2 r;
    r.x = fmaxf(fmaxf(a.x, a.y), fmaxf(c.x, c.y));
    r.y = fmaxf(fmaxf(a.z, a.w), fmaxf(c.z, c.w));
    *(float2*)&out[((size_t)bc * H2_ + oh) * W2_ + ow2 * 2] = r;
}

// ------------------------- row-pool [B][4096][128] -> [B][1024][128] -------------------------
__global__ void poolrows_kernel(const float* __restrict__ in, float* __restrict__ out, int n) {
    int i = blockIdx.x * blockDim.x + threadIdx.x;
    if (i >= n) return;                      // n = B*1024*32 (float4 units)
    int ic4 = i & 31;
    int kv  = (i >> 5) & 1023;
    int b   = i >> 15;
    int ph = kv >> 5, pw = kv & 31;
    int s00 = (ph * 2) * 64 + pw * 2;
    const float4* p = (const float4*)(in + ((size_t)b * NQ_ + s00) * IC_) + ic4;
    float4 a = p[0], c = p[32], d = p[64 * 32], e = p[65 * 32];
    float4 r;
    r.x = fmaxf(fmaxf(a.x, c.x), fmaxf(d.x, e.x));
    r.y = fmaxf(fmaxf(a.y, c.y), fmaxf(d.y, e.y));
    r.z = fmaxf(fmaxf(a.z, c.z), fmaxf(d.z, e.z));
    r.w = fmaxf(fmaxf(a.w, c.w), fmaxf(d.w, e.w));
    ((float4*)(out + ((size_t)b * NKV_ + kv) * IC_))[ic4] = r;
}

// ------------------------- warp-per-row softmax over 1024 -------------------------
__global__ void __launch_bounds__(256) softmax_kernel(float* __restrict__ S) {
    int warp = threadIdx.x >> 5, lane = threadIdx.x & 31;
    size_t row = (size_t)blockIdx.x * 8 + warp;
    float* p = S + row * NKV_ + lane * 4;
    float4 v[8];
    float mx = -INFINITY;
    #pragma unroll
    for (int j = 0; j < 8; ++j) {
        v[j] = *(const float4*)&p[j * 128];
        mx = fmaxf(mx, fmaxf(fmaxf(v[j].x, v[j].y), fmaxf(v[j].z, v[j].w)));
    }
    #pragma unroll
    for (int o = 16; o; o >>= 1) mx = fmaxf(mx, __shfl_xor_sync(0xffffffffu, mx, o));
    float s = 0.f;
    #pragma unroll
    for (int j = 0; j < 8; ++j) {
        v[j].x = __expf(v[j].x - mx);
        v[j].y = __expf(v[j].y - mx);
        v[j].z = __expf(v[j].z - mx);
        v[j].w = __expf(v[j].w - mx);
        s += (v[j].x + v[j].y) + (v[j].z + v[j].w);
    }
    #pragma unroll
    for (int o = 16; o; o >>= 1) s += __shfl_xor_sync(0xffffffffu, s, o);
    float inv = 1.f / s;
    #pragma unroll
    for (int j = 0; j < 8; ++j) {
        v[j].x *= inv; v[j].y *= inv; v[j].z *= inv; v[j].w *= inv;
        *(float4*)&p[j * 128] = v[j];
    }
}

// ------------------------- BatchNorm stats (deterministic, float4) -------------------------
__global__ void bnstats_kernel() {
    __shared__ float ss[256], ss2[256];
    int co = blockIdx.x, tid = threadIdx.x;
    float s = 0.f, s2 = 0.f;
    for (int i = tid; i < B_ * NQ_ / 4; i += 256) {
        int b = i >> 10, sp = (i & 1023) << 2;
        float4 v = *(const float4*)&d_wy[((size_t)b * C_ + co) * NQ_ + sp];
        s += (v.x + v.y) + (v.z + v.w);
        s2 += (v.x * v.x + v.y * v.y) + (v.z * v.z + v.w * v.w);
    }
    ss[tid] = s; ss2[tid] = s2;
    __syncthreads();
    for (int st = 128; st > 0; st >>= 1) {
        if (tid < st) { ss[tid] += ss[tid + st]; ss2[tid] += ss2[tid + st]; }
        __syncthreads();
    }
    if (tid == 0) {
        const float invN = 1.f / (B_ * NQ_);
        float mean = ss[0] * invN;
        float var  = ss2[0] * invN - mean * mean;
        d_mean[co] = mean;
        d_rstd[co] = rsqrtf(var + 1e-5f);
    }
}

// ------------------------- BN apply + residual + 2x upsample -------------------------
// One thread per source element-pair: reads wy/rgb once, writes 2 rows x float4.
__global__ void final_kernel(const float* __restrict__ gamma, const float* __restrict__ beta,
                             float* __restrict__ out, int n) {
    int i = blockIdx.x * blockDim.x + threadIdx.x;
    if (i >= n) return;                      // n = B*C*64*32
    int w2p = i & 31;                        // pair of pooled cols: 2*w2p, 2*w2p+1
    int h2  = (i >> 5) & 63;
    int co  = (i >> 11) & 255;
    int b   = i >> 19;
    size_t base = ((size_t)b * C_ + co) * NQ_ + h2 * W2_ + 2 * w2p;
    float mn = d_mean[co], rs = d_rstd[co], gm = gamma[co], bt = beta[co];
    float2 wyv = *(const float2*)&d_wy[base];
    float2 rgv = *(const float2*)&d_rgb_p[base];
    float va = (wyv.x - mn) * rs * gm + bt + rgv.x;
    float vb = (wyv.y - mn) * rs * gm + bt + rgv.y;
    float4 r = { va, va, vb, vb };
    size_t ob = (((size_t)b * C_ + co) * H_ + 2 * h2) * W_ + 4 * w2p;
    *(float4*)&out[ob]      = r;             // row 2*h2
    *(float4*)&out[ob + W_] = r;             // row 2*h2+1
}

// ------------------------- launch -------------------------
extern "C" void kernel_launch(void* const* d_in, const int* in_sizes, int n_in,
                              void* d_out, int out_size) {
    const float* rgb     = (const float*)d_in[0];
    const float* event_  = (const float*)d_in[1];
    const float* g_w     = (const float*)d_in[2];
    const float* g_b     = (const float*)d_in[3];
    const float* theta_w = (const float*)d_in[4];
    const float* theta_b = (const float*)d_in[5];
    const float* phi_w   = (const float*)d_in[6];
    const float* phi_b   = (const float*)d_in[7];
    const float* W_w     = (const float*)d_in[8];
    const float* W_b     = (const float*)d_in[9];
    const float* bn_g    = (const float*)d_in[10];
    const float* bn_b    = (const float*)d_in[11];
    float* out = (float*)d_out;

    float *rgb_p, *ev_p, *theta, *gconv, *pconv, *g, *phi, *S, *y, *wy;
    cudaGetSymbolAddress((void**)&rgb_p, d_rgb_p);
    cudaGetSymbolAddress((void**)&ev_p,  d_ev_p);
    cudaGetSymbolAddress((void**)&theta, d_theta);
    cudaGetSymbolAddress((void**)&gconv, d_gconv);
    cudaGetSymbolAddress((void**)&pconv, d_pconv);
    cudaGetSymbolAddress((void**)&g,     d_g);
    cudaGetSymbolAddress((void**)&phi,   d_phi);
    cudaGetSymbolAddress((void**)&S,     d_S);
    cudaGetSymbolAddress((void**)&y,     d_y);
    cudaGetSymbolAddress((void**)&wy,    d_wy);

    // 1) initial 2x2 maxpool on both modalities (2 outputs/thread)
    {
        int n = B_ * C_ * H2_ * W2_ / 2;
        pool2_kernel<<<(n + 255) / 256, 256>>>(rgb,    rgb_p, n);
        pool2_kernel<<<(n + 255) / 256, 256>>>(event_, ev_p,  n);
    }
    // 2) merged 1x1 conv projections (theta, g, phi) in one launch
    {
        dim3 grid(NQ_ / 128, 1, 24);
        gemm_proj<<<grid, 256>>>(rgb_p, ev_p, theta_w, theta_b, g_w, g_b,
                                 phi_w, phi_b, theta, gconv, pconv);
    }
    // 3) sub-sample pool for g and phi
    {
        int n = B_ * NKV_ * (IC_ / 4);
        poolrows_kernel<<<(n + 255) / 256, 256>>>(gconv, g,   n);
        poolrows_kernel<<<(n + 255) / 256, 256>>>(pconv, phi, n);
    }
    // 4a) scores: S[b][q][kv] = sum_c theta[b][q][c] phi[b][kv][c]
    {
        dim3 grid(NQ_ / 128, NKV_ / 128, B_);
        gemm_tc<false, false, 0><<<grid, 256>>>(theta, phi, nullptr, S,
            IC_, IC_, IC_, NKV_, (long)NQ_ * IC_, (long)NKV_ * IC_, (long)NQ_ * NKV_);
    }
    // 4b) softmax rows
    softmax_kernel<<<B_ * NQ_ / 8, 256>>>(S);
    // 4c) y[b][q][ic] = sum_kv P[b][q][kv] g[b][kv][ic]
    {
        dim3 grid(NQ_ / 128, 1, B_);
        gemm_tc<false, true, 0><<<grid, 256>>>(S, g, nullptr, y,
            NKV_, NKV_, IC_, IC_, (long)NQ_ * NKV_, (long)NKV_ * IC_, (long)NQ_ * IC_);
    }
    // 5) output conv: wy[b][co][s] = sum_ic W_w[co][ic] y[b][s][ic] + W_b[co]
    {
        dim3 grid(C_ / 128, NQ_ / 128, B_);
        gemm_tc<false, false, 2><<<grid, 256>>>(W_w, y, W_b, wy,
            IC_, IC_, IC_, NQ_, 0, (long)NQ_ * IC_, (long)C_ * NQ_);
    }
    // 6) BN stats
    bnstats_kernel<<<C_, 256>>>();
    // 7) BN apply + residual + 2x upsample
    {
        int n = B_ * C_ * H2_ * W2_ / 2;
        final_kernel<<<(n + 255) / 256, 256>>>(bn_g, bn_b, out, n);
    }
}

// round 15
// speedup vs baseline: 1.6305x; 1.0199x over previous
#include <cuda_runtime.h>
#include <cuda_bf16.h>
#include <math.h>

// Problem constants
#define B_   8
#define C_   256
#define IC_  128
#define H_   128
#define W_   128
#define H2_  64
#define W2_  64
#define NQ_  4096     // 64*64
#define NKV_ 1024     // 32*32

// ------------------------- scratch (device globals; no allocation) -------------------------
__device__ float d_rgb_p[B_ * C_ * NQ_];      // [B][C][4096]
__device__ float d_ev_p [B_ * C_ * NQ_];      // [B][C][4096]
__device__ float d_theta[B_ * NQ_ * IC_];     // [B][4096][128]
__device__ float d_gconv[B_ * NQ_ * IC_];     // pre-pool g
__device__ float d_pconv[B_ * NQ_ * IC_];     // pre-pool phi
__device__ float d_g    [B_ * NKV_ * IC_];    // [B][1024][128]
__device__ float d_phi  [B_ * NKV_ * IC_];    // [B][1024][128]
__device__ float d_S    [B_ * NQ_ * NKV_];    // [B][4096][1024] unnormalized exp(scores)
__device__ float d_y    [B_ * NQ_ * IC_];     // [B][4096][128]
__device__ float d_wy   [B_ * C_ * NQ_];      // [B][256][4096]
__device__ float d_mean [C_];
__device__ float d_rstd [C_];

// ------------------------- helpers -------------------------
// Split a pair of consecutive-k fp32 values into packed bf16x2 hi and lo.
// hi = bf16_rn(v); lo = bf16_rn(v - hi)  (v - hi is exact in fp32).
__device__ __forceinline__ void split2(float v0, float v1, unsigned &hi, unsigned &lo) {
    unsigned h;
    asm("cvt.rn.bf16x2.f32 %0, %1, %2;" : "=r"(h) : "f"(v1), "f"(v0));
    float h0 = __uint_as_float(h << 16);
    float h1 = __uint_as_float(h & 0xFFFF0000u);
    float r0 = v0 - h0, r1 = v1 - h1;
    asm("cvt.rn.bf16x2.f32 %0, %1, %2;" : "=r"(lo) : "f"(r1), "f"(r0));
    hi = h;
}

__device__ __forceinline__ void mma16(float* c, const unsigned* a, const unsigned* b) {
    asm volatile(
        "mma.sync.aligned.m16n8k16.row.col.f32.bf16.bf16.f32 "
        "{%0,%1,%2,%3}, {%4,%5,%6,%7}, {%8,%9}, {%0,%1,%2,%3};\n"
        : "+f"(c[0]), "+f"(c[1]), "+f"(c[2]), "+f"(c[3])
        : "r"(a[0]), "r"(a[1]), "r"(a[2]), "r"(a[3]), "r"(b[0]), "r"(b[1]));
}

__device__ __forceinline__ void cpa16(void* s, const void* g) {
    unsigned ss = (unsigned)__cvta_generic_to_shared(s);
    asm volatile("cp.async.cg.shared.global [%0], [%1], 16;\n" :: "r"(ss), "l"(g));
}
#define CP_COMMIT() asm volatile("cp.async.commit_group;\n")
#define CP_WAIT0()  asm volatile("cp.async.wait_group 0;\n" ::: "memory")

#define EXP_SHIFT 20.0f

// ------------------------- generic GEMM infrastructure -------------------------
// k-major: [k=16][val 128 pad 132]  (scalar frag loads conflict-free)
// m-major: [m/n=128][k=16 pad 20]   (float2 frag loads, <=2-way)
template<bool KMAJ> struct Tile;
template<> struct Tile<true>  { float d[2][16][132]; };
template<> struct Tile<false> { float d[2][128][20]; };

// ------------------------- 3-term split-bf16 GEMM body -------------------------
// EPI: 0 none, 1 bias per-n, 2 bias per-m, 3 exp(x - EXP_SHIFT) epilogue.
template<bool A_KMAJOR, bool B_KMAJOR, int EPI>
__device__ __forceinline__ void gemm_body(
    const float* __restrict__ Ag, const float* __restrict__ Bg,
    const float* __restrict__ bias, float* __restrict__ Cg,
    int K, int Astride, int Bstride, int Cstride, int m0, int n0,
    Tile<A_KMAJOR>& As, Tile<B_KMAJOR>& Bs)
{
    int tid = threadIdx.x;
    int lane = tid & 31, warp = tid >> 5;
    int wm = warp >> 2, wn = warp & 3;           // 2 x 4 warps; warp tile 64m x 32n
    float acc[4][4][4] = {};
    int nkt = K / 16;

    auto stage = [&](int kt, int bf) {
        if constexpr (A_KMAJOR) {
            #pragma unroll
            for (int i = 0; i < 2; ++i) {
                int o = tid + i * 256;
                int r = o >> 5, c = (o & 31) << 2;
                cpa16(&As.d[bf][r][c], &Ag[(size_t)(kt * 16 + r) * Astride + c]);
            }
        } else {
            #pragma unroll
            for (int i = 0; i < 2; ++i) {
                int o = tid + i * 256;
                int r = o >> 2, c = (o & 3) << 2;
                cpa16(&As.d[bf][r][c], &Ag[(size_t)r * Astride + kt * 16 + c]);
            }
        }
        if constexpr (B_KMAJOR) {
            #pragma unroll
            for (int i = 0; i < 2; ++i) {
                int o = tid + i * 256;
                int r = o >> 5, c = (o & 31) << 2;
                cpa16(&Bs.d[bf][r][c], &Bg[(size_t)(kt * 16 + r) * Bstride + c]);
            }
        } else {
            #pragma unroll
            for (int i = 0; i < 2; ++i) {
                int o = tid + i * 256;
                int r = o >> 2, c = (o & 3) << 2;
                cpa16(&Bs.d[bf][r][c], &Bg[(size_t)r * Bstride + kt * 16 + c]);
            }
        }
    };

    stage(0, 0);
    CP_COMMIT();
    CP_WAIT0();
    __syncthreads();

    for (int kt = 0; kt < nkt; ++kt) {
        int cur = kt & 1;
        if (kt + 1 < nkt) stage(kt + 1, cur ^ 1);
        CP_COMMIT();

        int kb = (lane & 3) * 2;
        unsigned ah[4][4], al[4][4], bh[4][2], bl[4][2];
        #pragma unroll
        for (int mi = 0; mi < 4; ++mi) {
            int mr = wm * 64 + mi * 16 + (lane >> 2);
            if constexpr (A_KMAJOR) {
                split2(As.d[cur][kb][mr],       As.d[cur][kb + 1][mr],       ah[mi][0], al[mi][0]);
                split2(As.d[cur][kb][mr + 8],   As.d[cur][kb + 1][mr + 8],   ah[mi][1], al[mi][1]);
                split2(As.d[cur][kb + 8][mr],   As.d[cur][kb + 9][mr],       ah[mi][2], al[mi][2]);
                split2(As.d[cur][kb + 8][mr + 8], As.d[cur][kb + 9][mr + 8], ah[mi][3], al[mi][3]);
            } else {
                float2 v;
                v = *(const float2*)&As.d[cur][mr][kb];         split2(v.x, v.y, ah[mi][0], al[mi][0]);
                v = *(const float2*)&As.d[cur][mr + 8][kb];     split2(v.x, v.y, ah[mi][1], al[mi][1]);
                v = *(const float2*)&As.d[cur][mr][kb + 8];     split2(v.x, v.y, ah[mi][2], al[mi][2]);
                v = *(const float2*)&As.d[cur][mr + 8][kb + 8]; split2(v.x, v.y, ah[mi][3], al[mi][3]);
            }
        }
        #pragma unroll
        for (int ni = 0; ni < 4; ++ni) {
            int nc = wn * 32 + ni * 8 + (lane >> 2);
            if constexpr (B_KMAJOR) {
                split2(Bs.d[cur][kb][nc],     Bs.d[cur][kb + 1][nc], bh[ni][0], bl[ni][0]);
                split2(Bs.d[cur][kb + 8][nc], Bs.d[cur][kb + 9][nc], bh[ni][1], bl[ni][1]);
            } else {
                float2 v;
                v = *(const float2*)&Bs.d[cur][nc][kb];     split2(v.x, v.y, bh[ni][0], bl[ni][0]);
                v = *(const float2*)&Bs.d[cur][nc][kb + 8]; split2(v.x, v.y, bh[ni][1], bl[ni][1]);
            }
        }
        #pragma unroll
        for (int mi = 0; mi < 4; ++mi)
            #pragma unroll
            for (int ni = 0; ni < 4; ++ni) {
                mma16(acc[mi][ni], al[mi], bh[ni]);   // lo*hi
                mma16(acc[mi][ni], ah[mi], bl[ni]);   // hi*lo
                mma16(acc[mi][ni], ah[mi], bh[ni]);   // hi*hi
            }

        CP_WAIT0();
        __syncthreads();
    }

    #pragma unroll
    for (int mi = 0; mi < 4; ++mi) {
        int r0 = m0 + wm * 64 + mi * 16 + (lane >> 2);
        #pragma unroll
        for (int ni = 0; ni < 4; ++ni) {
            int c0i = n0 + wn * 32 + ni * 8 + 2 * (lane & 3);
            float e0 = acc[mi][ni][0], e1 = acc[mi][ni][1];
            float e2 = acc[mi][ni][2], e3 = acc[mi][ni][3];
            if (EPI == 1) {
                float a0 = bias[c0i], a1 = bias[c0i + 1];
                e0 += a0; e1 += a1; e2 += a0; e3 += a1;
            }
            if (EPI == 2) {
                float a = bias[r0], bb = bias[r0 + 8];
                e0 += a; e1 += a; e2 += bb; e3 += bb;
            }
            if (EPI == 3) {
                e0 = __expf(e0 - EXP_SHIFT); e1 = __expf(e1 - EXP_SHIFT);
                e2 = __expf(e2 - EXP_SHIFT); e3 = __expf(e3 - EXP_SHIFT);
            }
            float2 v0 = { e0, e1 };
            float2 v1 = { e2, e3 };
            *(float2*)&Cg[(size_t)r0 * Cstride + c0i] = v0;
            *(float2*)&Cg[(size_t)(r0 + 8) * Cstride + c0i] = v1;
        }
    }
}

template<bool A_KMAJOR, bool B_KMAJOR, int EPI>
__global__ void __launch_bounds__(256) gemm_tc(
    const float* __restrict__ A, const float* __restrict__ Bm,
    const float* __restrict__ bias, float* __restrict__ Cm,
    int K, int Astride, int Bstride, int Cstride,
    long sAb, long sBb, long sCb)
{
    __shared__ Tile<A_KMAJOR> As;
    __shared__ Tile<B_KMAJOR> Bs;
    int m0 = blockIdx.x * 128, n0 = blockIdx.y * 128;
    int b = blockIdx.z;
    const float* Ag = A + (size_t)b * sAb;
    const float* Bg = Bm + (size_t)b * sBb;
    float* Cg = Cm + (size_t)b * sCb;
    if (A_KMAJOR) Ag += m0; else Ag += (size_t)m0 * Astride;
    if (B_KMAJOR) Bg += n0; else Bg += (size_t)n0 * Bstride;
    gemm_body<A_KMAJOR, B_KMAJOR, EPI>(
        Ag, Bg, bias, Cg, K, Astride, Bstride, Cstride, m0, n0, As, Bs);
}

// merged projection kernel (theta/g/phi), z = proj*8 + b
__global__ void __launch_bounds__(256) gemm_proj(
    const float* __restrict__ rgb_p, const float* __restrict__ ev_p,
    const float* __restrict__ tw, const float* __restrict__ tb,
    const float* __restrict__ gw, const float* __restrict__ gb,
    const float* __restrict__ pw, const float* __restrict__ pb,
    float* __restrict__ theta, float* __restrict__ gconv, float* __restrict__ pconv)
{
    __shared__ Tile<true> As;
    __shared__ Tile<false> Bs;
    int z = blockIdx.z;
    int pz = z >> 3, b = z & 7;
    const float* Aall = (pz == 0) ? rgb_p : ev_p;
    const float* Bw   = (pz == 0) ? tw : (pz == 1 ? gw : pw);
    const float* bias = (pz == 0) ? tb : (pz == 1 ? gb : pb);
    float* Cm         = (pz == 0) ? theta : (pz == 1 ? gconv : pconv);
    int m0 = blockIdx.x * 128;
    const float* Ag = Aall + (size_t)b * C_ * NQ_ + m0;   // k-major [256][4096]
    float* Cg = Cm + (size_t)b * NQ_ * IC_;
    gemm_body<true, false, 1>(Ag, Bw, bias, Cg, C_, NQ_, C_, IC_, m0, 0, As, Bs);
}

// ------------------------- PV GEMM with fused row-normalization -------------------------
// Y[b][q][ic] = (sum_kv P[b][q][kv] * G[b][kv][ic]) / (sum_kv P[b][q][kv])
// P = unnormalized exp(scores - EXP_SHIFT); the shift cancels in the division.
// Row sums accumulated from the fp32 smem P tiles during the mainloop (free).
__global__ void __launch_bounds__(256) gemm_pv(
    const float* __restrict__ P, const float* __restrict__ G, float* __restrict__ Y)
{
    __shared__ Tile<false> As;           // P tile, m-major [128][20]
    __shared__ Tile<true>  Bs;           // G tile, k-major [16][132]
    __shared__ float rs2[256];
    __shared__ float rsum[128];
    int tid = threadIdx.x;
    int lane = tid & 31, warp = tid >> 5;
    int wm = warp >> 2, wn = warp & 3;
    int m0 = blockIdx.x * 128, b = blockIdx.z;
    const float* Ag = P + (size_t)b * NQ_ * NKV_ + (size_t)m0 * NKV_;
    const float* Bg = G + (size_t)b * NKV_ * IC_;
    float* Cg = Y + ((size_t)b * NQ_ + m0) * IC_;
    float acc[4][4][4] = {};
    float rp = 0.f;                      // partial rowsum for row tid>>1, half tid&1
    int srow = tid >> 1, sh = (tid & 1) * 8;

    auto stage = [&](int kt, int bf) {
        #pragma unroll
        for (int i = 0; i < 2; ++i) {
            int o = tid + i * 256;
            int r = o >> 2, c = (o & 3) << 2;
            cpa16(&As.d[bf][r][c], &Ag[(size_t)r * NKV_ + kt * 16 + c]);
        }
        #pragma unroll
        for (int i = 0; i < 2; ++i) {
            int o = tid + i * 256;
            int r = o >> 5, c = (o & 31) << 2;
            cpa16(&Bs.d[bf][r][c], &Bg[(size_t)(kt * 16 + r) * IC_ + c]);
        }
    };

    stage(0, 0);
    CP_COMMIT();
    CP_WAIT0();
    __syncthreads();

    for (int kt = 0; kt < NKV_ / 16; ++kt) {
        int cur = kt & 1;
        if (kt + 1 < NKV_ / 16) stage(kt + 1, cur ^ 1);
        CP_COMMIT();

        // rowsum partial from the resident fp32 P tile
        #pragma unroll
        for (int j = 0; j < 8; ++j) rp += As.d[cur][srow][sh + j];

        int kb = (lane & 3) * 2;
        unsigned ah[4][4], al[4][4], bh[4][2], bl[4][2];
        #pragma unroll
        for (int mi = 0; mi < 4; ++mi) {
            int mr = wm * 64 + mi * 16 + (lane >> 2);
            float2 v;
            v = *(const float2*)&As.d[cur][mr][kb];         split2(v.x, v.y, ah[mi][0], al[mi][0]);
            v = *(const float2*)&As.d[cur][mr + 8][kb];     split2(v.x, v.y, ah[mi][1], al[mi][1]);
            v = *(const float2*)&As.d[cur][mr][kb + 8];     split2(v.x, v.y, ah[mi][2], al[mi][2]);
            v = *(const float2*)&As.d[cur][mr + 8][kb + 8]; split2(v.x, v.y, ah[mi][3], al[mi][3]);
        }
        #pragma unroll
        for (int ni = 0; ni < 4; ++ni) {
            int nc = wn * 32 + ni * 8 + (lane >> 2);
            split2(Bs.d[cur][kb][nc],     Bs.d[cur][kb + 1][nc], bh[ni][0], bl[ni][0]);
            split2(Bs.d[cur][kb + 8][nc], Bs.d[cur][kb + 9][nc], bh[ni][1], bl[ni][1]);
        }
        #pragma unroll
        for (int mi = 0; mi < 4; ++mi)
            #pragma unroll
            for (int ni = 0; ni < 4; ++ni) {
                mma16(acc[mi][ni], al[mi], bh[ni]);
                mma16(acc[mi][ni], ah[mi], bl[ni]);
                mma16(acc[mi][ni], ah[mi], bh[ni]);
            }

        CP_WAIT0();
        __syncthreads();
    }

    // reduce rowsums: rsum[r] = rs2[2r] + rs2[2r+1]
    rs2[tid] = rp;
    __syncthreads();
    if (tid < 128) rsum[tid] = rs2[2 * tid] + rs2[2 * tid + 1];
    __syncthreads();

    #pragma unroll
    for (int mi = 0; mi < 4; ++mi) {
        int rr = wm * 64 + mi * 16 + (lane >> 2);
        float inv0 = 1.f / rsum[rr], inv1 = 1.f / rsum[rr + 8];
        #pragma unroll
        for (int ni = 0; ni < 4; ++ni) {
            int c0i = wn * 32 + ni * 8 + 2 * (lane & 3);
            float2 v0 = { acc[mi][ni][0] * inv0, acc[mi][ni][1] * inv0 };
            float2 v1 = { acc[mi][ni][2] * inv1, acc[mi][ni][3] * inv1 };
            *(float2*)&Cg[(size_t)rr * IC_ + c0i] = v0;
            *(float2*)&Cg[(size_t)(rr + 8) * IC_ + c0i] = v1;
        }
    }
}

// ------------------------- 2x2 maxpool NCHW, vectorized (2 outputs/thread) -------------------------
__global__ void pool2_kernel(const float* __restrict__ in, float* __restrict__ out, int n) {
    int i = blockIdx.x * blockDim.x + threadIdx.x;
    if (i >= n) return;                      // n = B*C*64*32
    int ow2 = i & 31;
    int t  = i >> 5;
    int oh = t & 63;
    int bc = t >> 6;
    const float* p = in + ((size_t)bc * H_ + 2 * oh) * W_ + ow2 * 4;
    float4 a = *(const float4*)p;
    float4 c = *(const float4*)(p + W_);
    float2 r;
    r.x = fmaxf(fmaxf(a.x, a.y), fmaxf(c.x, c.y));
    r.y = fmaxf(fmaxf(a.z, a.w), fmaxf(c.z, c.w));
    *(float2*)&out[((size_t)bc * H2_ + oh) * W2_ + ow2 * 2] = r;
}

// ------------------------- row-pool [B][4096][128] -> [B][1024][128] -------------------------
__global__ void poolrows_kernel(const float* __restrict__ in, float* __restrict__ out, int n) {
    int i = blockIdx.x * blockDim.x + threadIdx.x;
    if (i >= n) return;                      // n = B*1024*32 (float4 units)
    int ic4 = i & 31;
    int kv  = (i >> 5) & 1023;
    int b   = i >> 15;
    int ph = kv >> 5, pw = kv & 31;
    int s00 = (ph * 2) * 64 + pw * 2;
    const float4* p = (const float4*)(in + ((size_t)b * NQ_ + s00) * IC_) + ic4;
    float4 a = p[0], c = p[32], d = p[64 * 32], e = p[65 * 32];
    float4 r;
    r.x = fmaxf(fmaxf(a.x, c.x), fmaxf(d.x, e.x));
    r.y = fmaxf(fmaxf(a.y, c.y), fmaxf(d.y, e.y));
    r.z = fmaxf(fmaxf(a.z, c.z), fmaxf(d.z, e.z));
    r.w = fmaxf(fmaxf(a.w, c.w), fmaxf(d.w, e.w));
    ((float4*)(out + ((size_t)b * NKV_ + kv) * IC_))[ic4] = r;
}

// ------------------------- BatchNorm stats (deterministic, float4) -------------------------
__global__ void bnstats_kernel() {
    __shared__ float ss[256], ss2[256];
    int co = blockIdx.x, tid = threadIdx.x;
    float s = 0.f, s2 = 0.f;
    for (int i = tid; i < B_ * NQ_ / 4; i += 256) {
        int b = i >> 10, sp = (i & 1023) << 2;
        float4 v = *(const float4*)&d_wy[((size_t)b * C_ + co) * NQ_ + sp];
        s += (v.x + v.y) + (v.z + v.w);
        s2 += (v.x * v.x + v.y * v.y) + (v.z * v.z + v.w * v.w);
    }
    ss[tid] = s; ss2[tid] = s2;
    __syncthreads();
    for (int st = 128; st > 0; st >>= 1) {
        if (tid < st) { ss[tid] += ss[tid + st]; ss2[tid] += ss2[tid + st]; }
        __syncthreads();
    }
    if (tid == 0) {
        const float invN = 1.f / (B_ * NQ_);
        float mean = ss[0] * invN;
        float var  = ss2[0] * invN - mean * mean;
        d_mean[co] = mean;
        d_rstd[co] = rsqrtf(var + 1e-5f);
    }
}

// ------------------------- BN apply + residual + 2x upsample -------------------------
__global__ void final_kernel(const float* __restrict__ gamma, const float* __restrict__ beta,
                             float* __restrict__ out, int n) {
    int i = blockIdx.x * blockDim.x + threadIdx.x;
    if (i >= n) return;                      // n = B*C*64*32
    int w2p = i & 31;                        // pair of pooled cols: 2*w2p, 2*w2p+1
    int h2  = (i >> 5) & 63;
    int co  = (i >> 11) & 255;
    int b   = i >> 19;
    size_t base = ((size_t)b * C_ + co) * NQ_ + h2 * W2_ + 2 * w2p;
    float mn = d_mean[co], rs = d_rstd[co], gm = gamma[co], bt = beta[co];
    float2 wyv = *(const float2*)&d_wy[base];
    float2 rgv = *(const float2*)&d_rgb_p[base];
    float va = (wyv.x - mn) * rs * gm + bt + rgv.x;
    float vb = (wyv.y - mn) * rs * gm + bt + rgv.y;
    float4 r = { va, va, vb, vb };
    size_t ob = (((size_t)b * C_ + co) * H_ + 2 * h2) * W_ + 4 * w2p;
    *(float4*)&out[ob]      = r;             // row 2*h2
    *(float4*)&out[ob + W_] = r;             // row 2*h2+1
}

// ------------------------- launch -------------------------
extern "C" void kernel_launch(void* const* d_in, const int* in_sizes, int n_in,
                              void* d_out, int out_size) {
    const float* rgb     = (const float*)d_in[0];
    const float* event_  = (const float*)d_in[1];
    const float* g_w     = (const float*)d_in[2];
    const float* g_b     = (const float*)d_in[3];
    const float* theta_w = (const float*)d_in[4];
    const float* theta_b = (const float*)d_in[5];
    const float* phi_w   = (const float*)d_in[6];
    const float* phi_b   = (const float*)d_in[7];
    const float* W_w     = (const float*)d_in[8];
    const float* W_b     = (const float*)d_in[9];
    const float* bn_g    = (const float*)d_in[10];
    const float* bn_b    = (const float*)d_in[11];
    float* out = (float*)d_out;

    float *rgb_p, *ev_p, *theta, *gconv, *pconv, *g, *phi, *S, *y, *wy;
    cudaGetSymbolAddress((void**)&rgb_p, d_rgb_p);
    cudaGetSymbolAddress((void**)&ev_p,  d_ev_p);
    cudaGetSymbolAddress((void**)&theta, d_theta);
    cudaGetSymbolAddress((void**)&gconv, d_gconv);
    cudaGetSymbolAddress((void**)&pconv, d_pconv);
    cudaGetSymbolAddress((void**)&g,     d_g);
    cudaGetSymbolAddress((void**)&phi,   d_phi);
    cudaGetSymbolAddress((void**)&S,     d_S);
    cudaGetSymbolAddress((void**)&y,     d_y);
    cudaGetSymbolAddress((void**)&wy,    d_wy);

    // 1) initial 2x2 maxpool on both modalities (2 outputs/thread)
    {
        int n = B_ * C_ * H2_ * W2_ / 2;
        pool2_kernel<<<(n + 255) / 256, 256>>>(rgb,    rgb_p, n);
        pool2_kernel<<<(n + 255) / 256, 256>>>(event_, ev_p,  n);
    }
    // 2) merged 1x1 conv projections (theta, g, phi) in one launch
    {
        dim3 grid(NQ_ / 128, 1, 24);
        gemm_proj<<<grid, 256>>>(rgb_p, ev_p, theta_w, theta_b, g_w, g_b,
                                 phi_w, phi_b, theta, gconv, pconv);
    }
    // 3) sub-sample pool for g and phi
    {
        int n = B_ * NKV_ * (IC_ / 4);
        poolrows_kernel<<<(n + 255) / 256, 256>>>(gconv, g,   n);
        poolrows_kernel<<<(n + 255) / 256, 256>>>(pconv, phi, n);
    }
    // 4a) scores + exp fused: S = exp(theta @ phi^T - 20)
    {
        dim3 grid(NQ_ / 128, NKV_ / 128, B_);
        gemm_tc<false, false, 3><<<grid, 256>>>(theta, phi, nullptr, S,
            IC_, IC_, IC_, NKV_, (long)NQ_ * IC_, (long)NKV_ * IC_, (long)NQ_ * NKV_);
    }
    // 4b) PV + row-normalization fused: y = (S @ g) / rowsum(S)
    {
        dim3 grid(NQ_ / 128, 1, B_);
        gemm_pv<<<grid, 256>>>(S, g, y);
    }
    // 5) output conv: wy[b][co][s] = sum_ic W_w[co][ic] y[b][s][ic] + W_b[co]
    {
        dim3 grid(C_ / 128, NQ_ / 128, B_);
        gemm_tc<false, false, 2><<<grid, 256>>>(W_w, y, W_b, wy,
            IC_, IC_, IC_, NQ_, 0, (long)NQ_ * IC_, (long)C_ * NQ_);
    }
    // 6) BN stats
    bnstats_kernel<<<C_, 256>>>();
    // 7) BN apply + residual + 2x upsample
    {
        int n = B_ * C_ * H2_ * W2_ / 2;
        final_kernel<<<(n + 255) / 256, 256>>>(bn_g, bn_b, out, n);
    }
}